// round 7
// baseline (speedup 1.0000x reference)
#include <cuda_runtime.h>
#include <cuda_bf16.h>
#include <cstdint>

#define BATCH 16384
#define NF 26
#define VOCAB 100000
#define ED 32
#define DIN 832
#define H1 256
#define H2 128
#define BN_EPS 1e-5f

#define NCHUNK 13        // 13 chunks x (2 fields = 64 k-cols bf16)
#define KSTEPS 52        // 832 / 16
#define NT1 32           // 256 / 8 n-tiles

// ---------------- scratch ----------------------------------------------------
__device__ float g_h1[BATCH * H1];
__device__ float g_h2[BATCH * H2];
__device__ float g_stats1[2 * H1];
__device__ float g_stats2[2 * H2];
__device__ float g_scale1[H1], g_shift1[H1];
__device__ float g_scale2[H2], g_shift2[H2];
// W1 packed as HMMA B-fragments: [kstep][ntile][lane] -> uint2{b0,b1}
__device__ __align__(16) uint2 g_w1f_hi[KSTEPS * NT1 * 32];
__device__ __align__(16) uint2 g_w1f_lo[KSTEPS * NT1 * 32];

__device__ __forceinline__ uint32_t smem_u32(const void* p) {
    uint32_t a;
    asm("{ .reg .u64 t; cvta.to.shared.u64 t, %1; cvt.u32.u64 %0, t; }" : "=r"(a) : "l"(p));
    return a;
}

__device__ __forceinline__ void split2(float x, float y, uint32_t& hi, uint32_t& lo) {
    __nv_bfloat162 h;
    h.x = __float2bfloat16_rn(x);
    h.y = __float2bfloat16_rn(y);
    __nv_bfloat162 l;
    l.x = __float2bfloat16_rn(x - __bfloat162float(h.x));
    l.y = __float2bfloat16_rn(y - __bfloat162float(h.y));
    hi = *(uint32_t*)&h;
    lo = *(uint32_t*)&l;
}

#define LDSM_X4(r, addr)                                                       \
    asm volatile("ldmatrix.sync.aligned.m8n8.x4.shared.b16 {%0,%1,%2,%3}, [%4];" \
                 : "=r"((r)[0]), "=r"((r)[1]), "=r"((r)[2]), "=r"((r)[3])      \
                 : "r"(addr))

#define MMA_BF16(d, a, b0, b1)                                                 \
    asm volatile(                                                              \
        "mma.sync.aligned.m16n8k16.row.col.f32.bf16.bf16.f32 "                 \
        "{%0,%1,%2,%3},{%4,%5,%6,%7},{%8,%9},{%0,%1,%2,%3};"                   \
        : "+f"((d)[0]), "+f"((d)[1]), "+f"((d)[2]), "+f"((d)[3])               \
        : "r"((a)[0]), "r"((a)[1]), "r"((a)[2]), "r"((a)[3]), "r"(b0), "r"(b1))

#define CP16(dst, src)                                                         \
    asm volatile("cp.async.cg.shared.global [%0], [%1], 16;"                   \
                 :: "r"(dst), "l"(src) : "memory")
#define CP_COMMIT() asm volatile("cp.async.commit_group;" ::: "memory")
#define CP_WAIT1()  asm volatile("cp.async.wait_group 1;" ::: "memory")
#define CP_WAIT0()  asm volatile("cp.async.wait_group 0;" ::: "memory")

__global__ void k_zero_stats() {
    int t = threadIdx.x;
    if (t < 2 * H1) g_stats1[t] = 0.f;
    if (t < 2 * H2) g_stats2[t] = 0.f;
}

// ---------------- W1 -> bf16 hi/lo HMMA B-fragment packing (split in 2 so the
// heavy fused kernel sits at launch position 4 for the profiler) --------------
template <int PART>
__global__ void k_prep_w1(const float* __restrict__ W1) {
    int g = blockIdx.x * blockDim.x + threadIdx.x;
    if (g >= KSTEPS * NT1 * 32) return;
    int lane = g & 31, nt = (g >> 5) & 31, ks = g >> 10;
    int k0 = ks * 16 + (lane & 3) * 2;
    int n = nt * 8 + (lane >> 2);
    float v00 = W1[(size_t)(k0 + 0) * H1 + n];
    float v01 = W1[(size_t)(k0 + 1) * H1 + n];
    float v10 = W1[(size_t)(k0 + 8) * H1 + n];
    float v11 = W1[(size_t)(k0 + 9) * H1 + n];
    uint2 hi, lo;
    split2(v00, v01, hi.x, lo.x);
    split2(v10, v11, hi.y, lo.y);
    if (PART == 0) g_w1f_hi[g] = hi;
    else           g_w1f_lo[g] = lo;
}

// =============================================================================
// Fused: gather + FM + HMMA GEMM1 (bf16 split-3) + bias + column stats.
// grid = 128 (BM=128), 256 threads (8 warps x 16 rows, N=256 full).
// B fragments double-buffered in smem via cp.async (hides L2 latency).
// =============================================================================
#define SM_SIDX  0                    // 128*26*4 = 13312
#define SM_SFM   13312                // 256 threads * 32 floats = 32768
#define SM_SSQ   46080                // 256 floats = 1024
#define SM_A     47104                // Ahi 16384 + Alo 16384
#define SM_B     79872                // 2 stages x (hi 32768 + lo 32768)
#define SM_TOT   210944

__global__ __launch_bounds__(256, 1) void k_fused1(
    const int* __restrict__ xc, const float* __restrict__ lin,
    const float* __restrict__ lat, const float* __restrict__ b1,
    const float* __restrict__ bias, float* __restrict__ out) {
    extern __shared__ char smem[];
    int* sidx = (int*)(smem + SM_SIDX);
    float* sfm = (float*)(smem + SM_SFM);
    float* ssqb = (float*)(smem + SM_SSQ);
    char* Ahi = smem + SM_A;
    char* Alo = smem + SM_A + 16384;

    const int tid = threadIdx.x;
    const int bm = blockIdx.x * 128;
    const uint32_t sb = smem_u32(smem);

    for (int i = tid; i < 128 * NF; i += 256) sidx[i] = xc[bm * NF + i];

    const int row = tid & 127, fpar = tid >> 7;   // gather mapping
    const int w = tid >> 5, lane = tid & 31;      // mma mapping
    const int g4 = lane >> 3;
    const int lr = w * 16 + (g4 & 1) * 8 + (lane & 7);
    const int qoff = g4 >> 1;

    float acc[NT1][4];
#pragma unroll
    for (int nt = 0; nt < NT1; nt++)
#pragma unroll
        for (int j = 0; j < 4; j++) acc[nt][j] = 0.f;
    float ssq = 0.f;

    // ---- cp.async issue helper for B chunk c into stage (c&1) ----
    auto issueB = [&](int c) {
        const char* gh = (const char*)(g_w1f_hi + (size_t)c * 4096);
        const char* gl = (const char*)(g_w1f_lo + (size_t)c * 4096);
        uint32_t dst = sb + SM_B + (uint32_t)(c & 1) * 65536;
#pragma unroll
        for (int i = 0; i < 8; i++)
            CP16(dst + tid * 16 + i * 4096, gh + tid * 16 + i * 4096);
#pragma unroll
        for (int i = 0; i < 8; i++)
            CP16(dst + 32768 + tid * 16 + i * 4096, gl + tid * 16 + i * 4096);
        CP_COMMIT();
    };

    issueB(0);
    issueB(1);
    __syncthreads();   // sidx visible

    for (int c = 0; c < NCHUNK; c++) {
        // ---- gather one field-row (32 fp32), FM, split, store swizzled -----
        {
            const int field = 2 * c + fpar;
            const size_t erow = (size_t)field * VOCAB + sidx[row * NF + field];
            const float4* src = (const float4*)(lat + erow * ED);
            float4 f[8];
#pragma unroll
            for (int j = 0; j < 8; j++) f[j] = __ldg(src + j);
            const float* ff = (const float*)f;
#pragma unroll
            for (int j = 0; j < 32; j++) ssq = fmaf(ff[j], ff[j], ssq);
            float4* sf4 = (float4*)sfm + tid * 8;
            if (c == 0) {
#pragma unroll
                for (int j = 0; j < 8; j++) sf4[j] = f[j];
            } else {
#pragma unroll
                for (int j = 0; j < 8; j++) {
                    float4 t = sf4[j];
                    t.x += f[j].x; t.y += f[j].y; t.z += f[j].z; t.w += f[j].w;
                    sf4[j] = t;
                }
            }
#pragma unroll
            for (int j2 = 0; j2 < 4; j2++) {
                float4 a = f[2 * j2], b = f[2 * j2 + 1];
                uint4 hq, lq;
                split2(a.x, a.y, hq.x, lq.x);
                split2(a.z, a.w, hq.y, lq.y);
                split2(b.x, b.y, hq.z, lq.z);
                split2(b.z, b.w, hq.w, lq.w);
                int q = fpar * 4 + j2;
                uint32_t off = (uint32_t)row * 128 + ((q ^ (row & 7)) << 4);
                *(uint4*)(Ahi + off) = hq;
                *(uint4*)(Alo + off) = lq;
            }
        }
        if (c == NCHUNK - 1) CP_WAIT0(); else CP_WAIT1();
        __syncthreads();

        // ---- MMA: 4 k-steps of 16 over this chunk, B frags from smem -------
        const char* Bst = smem + SM_B + (size_t)(c & 1) * 65536;
#pragma unroll
        for (int ks = 0; ks < 4; ks++) {
            uint32_t ah[4], al[4];
            int q = ks * 2 + qoff;
            uint32_t addr = sb + SM_A + (uint32_t)lr * 128 + ((q ^ (lr & 7)) << 4);
            LDSM_X4(ah, addr);
            LDSM_X4(al, addr + 16384);
            const uint2* bh = (const uint2*)(Bst) + (ks * 32) * 32 + lane;
            const uint2* bl = (const uint2*)(Bst + 32768) + (ks * 32) * 32 + lane;
#pragma unroll
            for (int nt = 0; nt < NT1; nt++) {
                uint2 B0 = bh[nt * 32];
                uint2 B1 = bl[nt * 32];
                MMA_BF16(acc[nt], ah, B0.x, B0.y);
                MMA_BF16(acc[nt], ah, B1.x, B1.y);
                MMA_BF16(acc[nt], al, B0.x, B0.y);
            }
        }
        __syncthreads();
        if (c + 2 < NCHUNK) issueB(c + 2);
    }

    // ---- FM logit -----------------------------------------------------------
    ssqb[tid] = ssq;
    __syncthreads();
    if (tid < 128) {
        const float4* sf4 = (const float4*)sfm;
        float sq = 0.f;
#pragma unroll
        for (int j = 0; j < 8; j++) {
            float4 u = sf4[tid * 8 + j];
            float4 v = sf4[(128 + tid) * 8 + j];
            float s0 = u.x + v.x, s1 = u.y + v.y, s2 = u.z + v.z, s3 = u.w + v.w;
            sq = fmaf(s0, s0, sq); sq = fmaf(s1, s1, sq);
            sq = fmaf(s2, s2, sq); sq = fmaf(s3, s3, sq);
        }
        float st = ssqb[tid] + ssqb[128 + tid];
        float lv = 0.f;
        for (int f = 0; f < NF; f++)
            lv += __ldg(lin + (size_t)f * VOCAB + sidx[tid * NF + f]);
        out[bm + tid] = lv + 0.5f * (sq - st) + bias[0];
    }

    // ---- epilogue: write h1 + column stats ----------------------------------
    float* ss = (float*)(smem + SM_A);           // 256 col sums
    float* qs = ss + 256;                        // 256 col sumsq
    ss[tid] = 0.f;
    qs[tid] = 0.f;
    __syncthreads();

    const int ra = bm + w * 16 + (lane >> 2);
    const int cb = (lane & 3) * 2;
#pragma unroll
    for (int nt = 0; nt < NT1; nt++) {
        int cc = nt * 8 + cb;
        float2 bb = *(const float2*)(b1 + cc);
        float h0 = acc[nt][0] + bb.x, h1 = acc[nt][1] + bb.y;
        float h2 = acc[nt][2] + bb.x, h3 = acc[nt][3] + bb.y;
        float2 r0v = make_float2(h0, h1), r1v = make_float2(h2, h3);
        *(float2*)(g_h1 + (size_t)ra * H1 + cc) = r0v;
        *(float2*)(g_h1 + (size_t)(ra + 8) * H1 + cc) = r1v;
        float s0 = h0 + h2, s1 = h1 + h3;
        float q0 = h0 * h0 + h2 * h2, q1 = h1 * h1 + h3 * h3;
#pragma unroll
        for (int o = 4; o <= 16; o <<= 1) {
            s0 += __shfl_xor_sync(0xffffffffu, s0, o);
            s1 += __shfl_xor_sync(0xffffffffu, s1, o);
            q0 += __shfl_xor_sync(0xffffffffu, q0, o);
            q1 += __shfl_xor_sync(0xffffffffu, q1, o);
        }
        if ((lane >> 2) == 0) {
            atomicAdd(&ss[cc], s0);
            atomicAdd(&ss[cc + 1], s1);
            atomicAdd(&qs[cc], q0);
            atomicAdd(&qs[cc + 1], q1);
        }
    }
    __syncthreads();
    atomicAdd(&g_stats1[tid], ss[tid]);
    atomicAdd(&g_stats1[H1 + tid], qs[tid]);
}

// ---------------- finalize BN ------------------------------------------------
template <int COLS>
__global__ void k_finalize(const float* __restrict__ g, const float* __restrict__ be) {
    const float* __restrict__ stats = (COLS == H1) ? g_stats1 : g_stats2;
    float* __restrict__ scale = (COLS == H1) ? g_scale1 : g_scale2;
    float* __restrict__ shift = (COLS == H1) ? g_shift1 : g_shift2;
    int t = threadIdx.x;
    const float inv = 1.f / (float)BATCH;
    float m = stats[t] * inv;
    float var = stats[COLS + t] * inv - m * m;
    float sc = g[t] * rsqrtf(var + BN_EPS);
    scale[t] = sc;
    shift[t] = be[t] - m * sc;
}

// =============================================================================
// GEMM2: h2 = relu(bn(h1)) @ W2 + b2 (+ column stats). BM=64, grid=256.
// =============================================================================
__global__ __launch_bounds__(256, 3) void k_gemm2(const float* __restrict__ W2,
                                                  const float* __restrict__ b2) {
    __shared__ float sm[16 * 64 + 16 * 128];
    float* As = sm;
    float* Bs = sm + 16 * 64;

    int tid = threadIdx.x;
    int bm = blockIdx.x * 64;
    int tx = tid & 15, ty = tid >> 4;

    float acc[4][8];
#pragma unroll
    for (int i = 0; i < 4; i++)
#pragma unroll
        for (int j = 0; j < 8; j++) acc[i][j] = 0.f;

    for (int k0 = 0; k0 < H1; k0 += 16) {
        {
            int rrow = tid >> 2, kq = tid & 3;
            int kb = k0 + kq * 4;
            float4 v = *(const float4*)(g_h1 + (size_t)(bm + rrow) * H1 + kb);
            v.x = fmaxf(fmaf(v.x, g_scale1[kb + 0], g_shift1[kb + 0]), 0.f);
            v.y = fmaxf(fmaf(v.y, g_scale1[kb + 1], g_shift1[kb + 1]), 0.f);
            v.z = fmaxf(fmaf(v.z, g_scale1[kb + 2], g_shift1[kb + 2]), 0.f);
            v.w = fmaxf(fmaf(v.w, g_scale1[kb + 3], g_shift1[kb + 3]), 0.f);
            As[(kq * 4 + 0) * 64 + rrow] = v.x;
            As[(kq * 4 + 1) * 64 + rrow] = v.y;
            As[(kq * 4 + 2) * 64 + rrow] = v.z;
            As[(kq * 4 + 3) * 64 + rrow] = v.w;
        }
#pragma unroll
        for (int l = 0; l < 2; l++) {
            int slot = tid + l * 256;
            int kr = slot >> 5, nq = slot & 31;
            *(float4*)(&Bs[kr * 128 + nq * 4]) =
                *(const float4*)(W2 + (size_t)(k0 + kr) * H2 + nq * 4);
        }
        __syncthreads();
#pragma unroll
        for (int kk = 0; kk < 16; kk++) {
            float ra[4], rb[8];
            *(float4*)(ra)     = *(const float4*)(&As[kk * 64 + ty * 4]);
            *(float4*)(rb)     = *(const float4*)(&Bs[kk * 128 + tx * 8]);
            *(float4*)(rb + 4) = *(const float4*)(&Bs[kk * 128 + tx * 8 + 4]);
#pragma unroll
            for (int i = 0; i < 4; i++)
#pragma unroll
                for (int j = 0; j < 8; j++) acc[i][j] = fmaf(ra[i], rb[j], acc[i][j]);
        }
        __syncthreads();
    }

    float bc[8];
    *(float4*)(bc)     = *(const float4*)(b2 + tx * 8);
    *(float4*)(bc + 4) = *(const float4*)(b2 + tx * 8 + 4);
    float csum[8], csq[8];
#pragma unroll
    for (int j = 0; j < 8; j++) { csum[j] = 0.f; csq[j] = 0.f; }
#pragma unroll
    for (int i = 0; i < 4; i++) {
        int r = bm + ty * 4 + i;
        float hh[8];
#pragma unroll
        for (int j = 0; j < 8; j++) {
            hh[j] = acc[i][j] + bc[j];
            csum[j] += hh[j];
            csq[j] = fmaf(hh[j], hh[j], csq[j]);
        }
        *(float4*)(g_h2 + (size_t)r * H2 + tx * 8)     = *(float4*)(hh);
        *(float4*)(g_h2 + (size_t)r * H2 + tx * 8 + 4) = *(float4*)(hh + 4);
    }
    float* red = sm;
#pragma unroll
    for (int j = 0; j < 8; j++) red[ty * 128 + tx * 8 + j] = csum[j];
    __syncthreads();
    if (tid < 128) {
        float v = 0.f;
#pragma unroll
        for (int y = 0; y < 16; y++) v += red[y * 128 + tid];
        atomicAdd(&g_stats2[tid], v);
    }
    __syncthreads();
#pragma unroll
    for (int j = 0; j < 8; j++) red[ty * 128 + tx * 8 + j] = csq[j];
    __syncthreads();
    if (tid < 128) {
        float v = 0.f;
#pragma unroll
        for (int y = 0; y < 16; y++) v += red[y * 128 + tid];
        atomicAdd(&g_stats2[H2 + tid], v);
    }
}

// ---------------- final layer ------------------------------------------------
__global__ void k_final(const float* __restrict__ W3, const float* __restrict__ b3,
                        float* __restrict__ out) {
    int warp = (blockIdx.x * blockDim.x + threadIdx.x) >> 5;
    int lane = threadIdx.x & 31;
    if (warp >= BATCH) return;
    float acc = 0.f;
#pragma unroll
    for (int j0 = 0; j0 < H2; j0 += 32) {
        int j = j0 + lane;
        float v = g_h2[(size_t)warp * H2 + j];
        float a = fmaxf(fmaf(v, g_scale2[j], g_shift2[j]), 0.f);
        acc = fmaf(a, W3[j], acc);
    }
#pragma unroll
    for (int o = 16; o; o >>= 1) acc += __shfl_xor_sync(0xffffffffu, acc, o);
    if (lane == 0) out[warp] += acc + b3[0];
}

// -----------------------------------------------------------------------------
extern "C" void kernel_launch(void* const* d_in, const int* in_sizes, int n_in,
                              void* d_out, int out_size) {
    const int*   xc   = (const int*)d_in[0];
    const float* lin  = (const float*)d_in[1];
    const float* lat  = (const float*)d_in[2];
    const float* W1   = (const float*)d_in[3];
    const float* b1   = (const float*)d_in[4];
    const float* g1   = (const float*)d_in[5];
    const float* be1  = (const float*)d_in[6];
    const float* W2   = (const float*)d_in[7];
    const float* b2   = (const float*)d_in[8];
    const float* g2   = (const float*)d_in[9];
    const float* be2  = (const float*)d_in[10];
    const float* W3   = (const float*)d_in[11];
    const float* b3   = (const float*)d_in[12];
    const float* bias = (const float*)d_in[13];
    float* out = (float*)d_out;

    cudaFuncSetAttribute(k_fused1, cudaFuncAttributeMaxDynamicSharedMemorySize,
                         SM_TOT);

    const int prep_grid = (KSTEPS * NT1 * 32 + 255) / 256;
    k_prep_w1<0><<<prep_grid, 256>>>(W1);          // launch 1
    k_prep_w1<1><<<prep_grid, 256>>>(W1);          // launch 2
    k_zero_stats<<<1, 512>>>();                    // launch 3
    k_fused1<<<BATCH / 128, 256, SM_TOT>>>(xc, lin, lat, b1, bias, out);  // launch 4 (profiled)
    k_finalize<H1><<<1, H1>>>(g1, be1);
    k_gemm2<<<BATCH / 64, 256>>>(W2, b2);
    k_finalize<H2><<<1, H2>>>(g2, be2);
    k_final<<<BATCH / 8, 256>>>(W3, b3, out);
}